// round 7
// baseline (speedup 1.0000x reference)
#include <cuda_runtime.h>

typedef unsigned long long u64;

#define Bb 64
#define Tt 512
#define Dd 1024
#define Hh 1024
#define Gblk 128   // persistent grid size (co-resident on 148 SMs)

// Scratch (allocation-free rule: __device__ globals)
__device__ float g_Gx[(size_t)Tt * Bb * 2 * Hh];  // [t][b][2H] = x@W[:D] + W_b
__device__ float g_Cx[(size_t)Tt * Bb * Hh];      // [t][b][H]  = x@U[:D] + U_b
__device__ float g_h [Bb * Hh];                   // hidden state [b][H]
__device__ float g_rh[Bb * Hh];                   // r * h
__device__ float g_u [Bb * Hh];                   // update gate
__device__ float g_pA[4 * Bb * 2 * Hh];           // gate partials [ksplit][b][2H]
__device__ float g_pB[8 * Bb * Hh];               // cand partials [ksplit][b][H]
__device__ unsigned g_arrive;                     // monotonic barrier counter

// ---- packed f32x2 helpers ----
__device__ __forceinline__ void fma2(u64 &d, u64 a, u64 b) {
    asm("fma.rn.f32x2 %0, %1, %2, %0;" : "+l"(d) : "l"(a), "l"(b));
}
__device__ __forceinline__ float2 unpack2(u64 v) {
    float2 f; asm("mov.b64 {%0, %1}, %2;" : "=f"(f.x), "=f"(f.y) : "l"(v)); return f;
}
__device__ __forceinline__ unsigned ld_acq(const unsigned* p) {
    unsigned v; asm volatile("ld.global.acquire.gpu.u32 %0, [%1];" : "=r"(v) : "l"(p)); return v;
}
__device__ __forceinline__ void red_release(unsigned* p) {
    asm volatile("red.release.gpu.global.add.u32 [%0], 1;" :: "l"(p) : "memory");
}
__device__ __forceinline__ void prefetch_l2(const void* p) {
    asm volatile("prefetch.global.L2 [%0];" :: "l"(p));
}
__device__ __forceinline__ float sigf(float x) {
    return __fdividef(1.0f, 1.0f + __expf(-x));
}
__device__ __forceinline__ float tanh_fast(float x) {
    float e = __expf(-2.0f * x);
    return __fdividef(1.0f - e, 1.0f + e);
}

// Duplicated-h staging layout: 32 k-rows, each row = 16 groups of 4 rows.
// group stride 48B (4 x float2 = 32B data + 16B pad) -> the 8 tm-groups a warp
// touches land on 8 distinct 16B-bank sets (g*12 banks mod 32 all distinct).
#define HSD_ROW   768                    // 16 groups * 48B
#define HSD_BYTES (32 * HSD_ROW)         // 24 KB

// Stage one float4 (4 consecutive k of one row m) into duplicated layout.
__device__ __forceinline__ void stage_dup(char* hsd, int m, int kq, float4 v) {
    int goff = (m >> 2) * 48 + (m & 3) * 8;
    *reinterpret_cast<float2*>(hsd + (size_t)(kq + 0) * HSD_ROW + goff) = make_float2(v.x, v.x);
    *reinterpret_cast<float2*>(hsd + (size_t)(kq + 1) * HSD_ROW + goff) = make_float2(v.y, v.y);
    *reinterpret_cast<float2*>(hsd + (size_t)(kq + 2) * HSD_ROW + goff) = make_float2(v.z, v.z);
    *reinterpret_cast<float2*>(hsd + (size_t)(kq + 3) * HSD_ROW + goff) = make_float2(v.w, v.w);
}

// Inner 32-k product: acc[4 rows][2 colpairs] += a_dup * w
__device__ __forceinline__ void mac32(u64 (&acc)[4][2], const char* hbase,
                                      const float* __restrict__ wsl, int tn) {
#pragma unroll
    for (int k = 0; k < 32; k++) {
        ulonglong2 a01 = *reinterpret_cast<const ulonglong2*>(hbase + k * HSD_ROW);
        ulonglong2 a23 = *reinterpret_cast<const ulonglong2*>(hbase + k * HSD_ROW + 16);
        ulonglong2 wv  = *reinterpret_cast<const ulonglong2*>(&wsl[k * 64 + tn * 4]);
        fma2(acc[0][0], a01.x, wv.x); fma2(acc[0][1], a01.x, wv.y);
        fma2(acc[1][0], a01.y, wv.x); fma2(acc[1][1], a01.y, wv.y);
        fma2(acc[2][0], a23.x, wv.x); fma2(acc[2][1], a23.x, wv.y);
        fma2(acc[3][0], a23.y, wv.x); fma2(acc[3][1], a23.y, wv.y);
    }
}

// ============================================================================
// Precompute GEMM: out[(t*64+b), n] = x[b,t,:] @ Wm[:D, n0..] + bias
// 64x64 tile, 256 threads, thread = 4 rows x 4 cols (col-pair packed).
// warp = 8 tm-groups x 4 tn-groups.
// ============================================================================
__global__ void __launch_bounds__(256) gemm_pre(
    const float* __restrict__ X, const float* __restrict__ Wm,
    const float* __restrict__ bias, int N, int which)
{
    float* __restrict__ out = which ? g_Cx : g_Gx;
    const int t   = blockIdx.y;
    const int n0  = blockIdx.x * 64;
    const int tid = threadIdx.x;
    const int lane = tid & 31, warp = tid >> 5;
    const int tm = (lane & 7) | ((warp & 1) << 3);
    const int tn = ((lane >> 3) & 3) | ((warp >> 1) << 2);

    __shared__ __align__(16) char hsd[HSD_BYTES];
    __shared__ float ws[32 * 64];

    u64 acc[4][2];
#pragma unroll
    for (int r = 0; r < 4; r++) { acc[r][0] = 0ull; acc[r][1] = 0ull; }

    float4 pa[2], pb[2];
#pragma unroll
    for (int i = 0; i < 2; i++) {
        int idx = tid + i * 256;
        int m = idx & 63, kq = (idx >> 6) * 4;
        pa[i] = *reinterpret_cast<const float4*>(&X[(size_t)(m * Tt + t) * Dd + kq]);
        int n4 = (idx & 15) * 4, kk = idx >> 4;
        pb[i] = *reinterpret_cast<const float4*>(&Wm[(size_t)kk * N + n0 + n4]);
    }

    const char* hbase = hsd + tm * 48;

    for (int kt = 0; kt < Dd / 32; ++kt) {
#pragma unroll
        for (int i = 0; i < 2; i++) {
            int idx = tid + i * 256;
            int m = idx & 63, kq = (idx >> 6) * 4;
            stage_dup(hsd, m, kq, pa[i]);
            int n4 = (idx & 15) * 4, kk = idx >> 4;
            *reinterpret_cast<float4*>(&ws[kk * 64 + n4]) = pb[i];
        }
        __syncthreads();
        if (kt + 1 < Dd / 32) {
            int k0 = (kt + 1) * 32;
#pragma unroll
            for (int i = 0; i < 2; i++) {
                int idx = tid + i * 256;
                int m = idx & 63, kq = (idx >> 6) * 4;
                pa[i] = *reinterpret_cast<const float4*>(&X[(size_t)(m * Tt + t) * Dd + k0 + kq]);
                int n4 = (idx & 15) * 4, kk = idx >> 4;
                pb[i] = *reinterpret_cast<const float4*>(&Wm[(size_t)(k0 + kk) * N + n0 + n4]);
            }
        }
        mac32(acc, hbase, ws, tn);
        __syncthreads();
    }

    const int n = n0 + tn * 4;
    float4 bv = *reinterpret_cast<const float4*>(&bias[n]);
#pragma unroll
    for (int r = 0; r < 4; r++) {
        float2 u0 = unpack2(acc[r][0]), u1 = unpack2(acc[r][1]);
        float4 o = make_float4(u0.x + bv.x, u0.y + bv.y, u1.x + bv.z, u1.y + bv.w);
        *reinterpret_cast<float4*>(&out[(size_t)(t * Bb + tm * 4 + r) * N + n]) = o;
    }
}

__global__ void copy_h0(const float* __restrict__ h0)
{
    int i = blockIdx.x * blockDim.x + threadIdx.x;
    if (i < Bb * Hh) g_h[i] = h0[i];
}

// ============================================================================
// Persistent recurrence. Per step: A (gate partials) | A-red (sigmoid) |
// B (cand partials) | B-red (tanh + update). 4 fence-free grid barriers.
// Weight slices resident in dynamic smem for all 512 steps.
// ============================================================================
#define SM_WA (256 * 64)   // phase A weights [256k][64c] floats
#define SM_WB (128 * 64)   // phase B weights [128k][64c] floats
#define SMEM_BYTES ((SM_WA + SM_WB) * 4 + HSD_BYTES)

__global__ void __launch_bounds__(256) gru_persist(
    const float* __restrict__ W, const float* __restrict__ U,
    float* __restrict__ out)
{
    extern __shared__ float sm[];
    float* __restrict__ wA = sm;
    float* __restrict__ wB = sm + SM_WA;
    char*  hsd = reinterpret_cast<char*>(sm + SM_WA + SM_WB);

    const int tid = threadIdx.x;
    const int bx  = blockIdx.x;
    const int lane = tid & 31, warp = tid >> 5;
    const int tm = (lane & 7) | ((warp & 1) << 3);
    const int tn = ((lane >> 3) & 3) | ((warp >> 1) << 2);
    const int ca = bx & 31, sa = bx >> 5;   // phase A: 32 colblocks x 4 ksplits
    const int cb = bx & 15, sb = bx >> 4;   // phase B: 16 colblocks x 8 ksplits

    // ---- preload weight slices into smem (once per launch) ----
    for (int i = tid; i < 256 * 16; i += 256) {
        int k = i >> 4, c4 = (i & 15) * 4;
        *reinterpret_cast<float4*>(&wA[k * 64 + c4]) =
            *reinterpret_cast<const float4*>(&W[(size_t)(Dd + sa * 256 + k) * (2 * Hh) + ca * 64 + c4]);
    }
    for (int i = tid; i < 128 * 16; i += 256) {
        int k = i >> 4, c4 = (i & 15) * 4;
        *reinterpret_cast<float4*>(&wB[k * 64 + c4]) =
            *reinterpret_cast<const float4*>(&U[(size_t)(Dd + sb * 128 + k) * Hh + cb * 64 + c4]);
    }
    __syncthreads();

    const unsigned base = ld_acq(&g_arrive);
    unsigned epoch = 0;
    const char* hbase = hsd + tm * 48;

#define GRID_BAR()                                                          \
    do {                                                                    \
        __syncthreads();                                                    \
        epoch++;                                                            \
        if (tid == 0) {                                                     \
            red_release(&g_arrive);                                         \
            while ((unsigned)(ld_acq(&g_arrive) - base) < epoch * Gblk) ;   \
        }                                                                   \
        __syncthreads();                                                    \
    } while (0)

    for (int t = 0; t < Tt; ++t) {
        // L2 prefetch of the Gx / Cx slices the reduce phases will read
        if (tid < 32)
            prefetch_l2(reinterpret_cast<const char*>(g_Gx) +
                        ((size_t)t * Bb * 2 * Hh + bx * 1024) * 4 + tid * 128);
        else if (tid < 48)
            prefetch_l2(reinterpret_cast<const char*>(g_Cx) +
                        ((size_t)t * Bb * Hh + bx * 512) * 4 + (tid - 32) * 128);

        // ---------------- Phase A: gate partials ----------------
        {
            u64 acc[4][2];
#pragma unroll
            for (int r = 0; r < 4; r++) { acc[r][0] = 0ull; acc[r][1] = 0ull; }

            float4 pa[2];
#pragma unroll
            for (int i = 0; i < 2; i++) {
                int idx = tid + i * 256;
                int m = idx & 63, kq = (idx >> 6) * 4;
                pa[i] = *reinterpret_cast<const float4*>(&g_h[m * Hh + sa * 256 + kq]);
            }
            for (int kt = 0; kt < 8; ++kt) {
#pragma unroll
                for (int i = 0; i < 2; i++) {
                    int idx = tid + i * 256;
                    int m = idx & 63, kq = (idx >> 6) * 4;
                    stage_dup(hsd, m, kq, pa[i]);
                }
                __syncthreads();
                if (kt + 1 < 8) {
                    int k0 = sa * 256 + (kt + 1) * 32;
#pragma unroll
                    for (int i = 0; i < 2; i++) {
                        int idx = tid + i * 256;
                        int m = idx & 63, kq = (idx >> 6) * 4;
                        pa[i] = *reinterpret_cast<const float4*>(&g_h[m * Hh + k0 + kq]);
                    }
                }
                mac32(acc, hbase, &wA[kt * 32 * 64], tn);
                __syncthreads();
            }
#pragma unroll
            for (int r = 0; r < 4; r++) {
                float2 u0 = unpack2(acc[r][0]), u1 = unpack2(acc[r][1]);
                float4 o = make_float4(u0.x, u0.y, u1.x, u1.y);
                *reinterpret_cast<float4*>(
                    &g_pA[(size_t)sa * (Bb * 2 * Hh) + (tm * 4 + r) * (2 * Hh) + ca * 64 + tn * 4]) = o;
            }
        }
        GRID_BAR();

        // ---------------- A-reduce: sigmoid gates ----------------
        {
            const int flat = bx * 1024 + tid * 4;     // = b*2048 + n
            float4 s0 = *reinterpret_cast<const float4*>(&g_pA[0 * (Bb * 2 * Hh) + flat]);
            float4 s1 = *reinterpret_cast<const float4*>(&g_pA[1 * (Bb * 2 * Hh) + flat]);
            float4 s2 = *reinterpret_cast<const float4*>(&g_pA[2 * (Bb * 2 * Hh) + flat]);
            float4 s3 = *reinterpret_cast<const float4*>(&g_pA[3 * (Bb * 2 * Hh) + flat]);
            float4 gx = *reinterpret_cast<const float4*>(&g_Gx[(size_t)t * (Bb * 2 * Hh) + flat]);
            float4 g;
            g.x = sigf(s0.x + s1.x + s2.x + s3.x + gx.x);
            g.y = sigf(s0.y + s1.y + s2.y + s3.y + gx.y);
            g.z = sigf(s0.z + s1.z + s2.z + s3.z + gx.z);
            g.w = sigf(s0.w + s1.w + s2.w + s3.w + gx.w);
            const int hidx = (bx >> 1) * 1024 + tid * 4;
            if (bx & 1) {
                *reinterpret_cast<float4*>(&g_u[hidx]) = g;
            } else {
                float4 h4 = *reinterpret_cast<const float4*>(&g_h[hidx]);
                float4 rh; rh.x = g.x * h4.x; rh.y = g.y * h4.y;
                rh.z = g.z * h4.z; rh.w = g.w * h4.w;
                *reinterpret_cast<float4*>(&g_rh[hidx]) = rh;
            }
        }
        GRID_BAR();

        // ---------------- Phase B: candidate partials ----------------
        {
            u64 acc[4][2];
#pragma unroll
            for (int r = 0; r < 4; r++) { acc[r][0] = 0ull; acc[r][1] = 0ull; }

            float4 pa[2];
#pragma unroll
            for (int i = 0; i < 2; i++) {
                int idx = tid + i * 256;
                int m = idx & 63, kq = (idx >> 6) * 4;
                pa[i] = *reinterpret_cast<const float4*>(&g_rh[m * Hh + sb * 128 + kq]);
            }
            for (int kt = 0; kt < 4; ++kt) {
#pragma unroll
                for (int i = 0; i < 2; i++) {
                    int idx = tid + i * 256;
                    int m = idx & 63, kq = (idx >> 6) * 4;
                    stage_dup(hsd, m, kq, pa[i]);
                }
                __syncthreads();
                if (kt + 1 < 4) {
                    int k0 = sb * 128 + (kt + 1) * 32;
#pragma unroll
                    for (int i = 0; i < 2; i++) {
                        int idx = tid + i * 256;
                        int m = idx & 63, kq = (idx >> 6) * 4;
                        pa[i] = *reinterpret_cast<const float4*>(&g_rh[m * Hh + k0 + kq]);
                    }
                }
                mac32(acc, hbase, &wB[kt * 32 * 64], tn);
                __syncthreads();
            }
#pragma unroll
            for (int r = 0; r < 4; r++) {
                float2 u0 = unpack2(acc[r][0]), u1 = unpack2(acc[r][1]);
                float4 o = make_float4(u0.x, u0.y, u1.x, u1.y);
                *reinterpret_cast<float4*>(
                    &g_pB[(size_t)sb * (Bb * Hh) + (tm * 4 + r) * Hh + cb * 64 + tn * 4]) = o;
            }
        }
        GRID_BAR();

        // ---------------- B-reduce: tanh + state update ----------------
        {
            const int flat = bx * 512 + tid * 2;      // = b*1024 + n
            float2 acc2 = *reinterpret_cast<const float2*>(&g_Cx[(size_t)t * (Bb * Hh) + flat]);
#pragma unroll
            for (int s = 0; s < 8; s++) {
                float2 p = *reinterpret_cast<const float2*>(&g_pB[(size_t)s * (Bb * Hh) + flat]);
                acc2.x += p.x; acc2.y += p.y;
            }
            float2 u2 = *reinterpret_cast<const float2*>(&g_u[flat]);
            float2 h2 = *reinterpret_cast<const float2*>(&g_h[flat]);
            float2 hn;
            hn.x = u2.x * h2.x + (1.0f - u2.x) * tanh_fast(acc2.x);
            hn.y = u2.y * h2.y + (1.0f - u2.y) * tanh_fast(acc2.y);
            *reinterpret_cast<float2*>(&g_h[flat]) = hn;
            const int b = flat >> 10, n = flat & 1023;
            *reinterpret_cast<float2*>(&out[((size_t)b * Tt + t) * Hh + n]) = hn;
        }
        GRID_BAR();
    }
#undef GRID_BAR
}

extern "C" void kernel_launch(void* const* d_in, const int* in_sizes, int n_in,
                              void* d_out, int out_size)
{
    const float* x  = (const float*)d_in[0];
    const float* h0 = (const float*)d_in[1];
    const float* W  = (const float*)d_in[2];
    const float* Wb = (const float*)d_in[3];
    const float* U  = (const float*)d_in[4];
    const float* Ub = (const float*)d_in[5];
    float* out = (float*)d_out;

    cudaFuncSetAttribute(gru_persist, cudaFuncAttributeMaxDynamicSharedMemorySize,
                         SMEM_BYTES);

    copy_h0<<<(Bb * Hh) / 256, 256>>>(h0);

    gemm_pre<<<dim3((2 * Hh) / 64, Tt), 256>>>(x, W, Wb, 2 * Hh, 0);
    gemm_pre<<<dim3(Hh / 64, Tt), 256>>>(x, U, Ub, Hh, 1);

    gru_persist<<<Gblk, 256, SMEM_BYTES>>>(W, U, out);
}

// round 10
// speedup vs baseline: 2.5755x; 2.5755x over previous
#include <cuda_runtime.h>
#include <cuda_bf16.h>

typedef unsigned int u32;
typedef unsigned long long u64;

#define Bb 64
#define Tt 512
#define Dd 1024
#define Hh 1024
#define Gblk 128

// ---------------- global scratch (allocation-free rule) ----------------
__device__ float g_Gx[(size_t)Tt * Bb * 2048];   // [t][b][n]
__device__ float g_Cx[(size_t)Tt * Bb * 1024];   // [t][b][n]
__device__ float g_h [Bb * Hh];                  // [b][c]
__device__ float g_rh[Bb * Hh];
__device__ float g_u [Bb * Hh];
__device__ float g_pA[(size_t)4 * Bb * 2048];    // [ksplit][b][n]
__device__ float g_pB[(size_t)8 * Bb * 1024];
__device__ __nv_bfloat16 g_xhi[(size_t)Bb * Tt * Dd];
__device__ __nv_bfloat16 g_xlo[(size_t)Bb * Tt * Dd];
__device__ __nv_bfloat16 g_Whi[2048 * 2048];
__device__ __nv_bfloat16 g_Wlo[2048 * 2048];
__device__ __nv_bfloat16 g_Uhi[2048 * 1024];
__device__ __nv_bfloat16 g_Ulo[2048 * 1024];
__device__ unsigned g_arrive;

// ---------------- helpers ----------------
__device__ __forceinline__ unsigned ld_acq(const unsigned* p) {
    unsigned v; asm volatile("ld.global.acquire.gpu.u32 %0, [%1];" : "=r"(v) : "l"(p)); return v;
}
__device__ __forceinline__ void red_release(unsigned* p) {
    asm volatile("red.release.gpu.global.add.u32 [%0], 1;" :: "l"(p) : "memory");
}
__device__ __forceinline__ float sigf(float x) { return __fdividef(1.0f, 1.0f + __expf(-x)); }
__device__ __forceinline__ float tanh_fast(float x) {
    float e = __expf(-2.0f * x);
    return __fdividef(1.0f - e, 1.0f + e);
}
__device__ __forceinline__ u32 smem_u32(const void* p) {
    u32 a; asm("{ .reg .u64 t; cvta.to.shared.u64 t, %1; cvt.u32.u64 %0, t; }" : "=r"(a) : "l"(p));
    return a;
}
__device__ __forceinline__ u32 pk(__nv_bfloat16 a, __nv_bfloat16 b) {
    __nv_bfloat162 t; t.x = a; t.y = b; return *reinterpret_cast<u32*>(&t);
}
__device__ __forceinline__ __nv_bfloat16 bfh(float x) { return __float2bfloat16_rn(x); }
__device__ __forceinline__ __nv_bfloat16 bfl(float x, __nv_bfloat16 h) {
    return __float2bfloat16_rn(x - __bfloat162float(h));
}

// ---------------- tensor-core primitives (baseline PTX, sm_80+) ----------------
__device__ __forceinline__ void ldm4(u32* r, u32 a) {
    asm volatile("ldmatrix.sync.aligned.m8n8.x4.shared.b16 {%0,%1,%2,%3}, [%4];"
        : "=r"(r[0]), "=r"(r[1]), "=r"(r[2]), "=r"(r[3]) : "r"(a));
}
__device__ __forceinline__ void ldm4t(u32* r, u32 a) {
    asm volatile("ldmatrix.sync.aligned.m8n8.x4.trans.shared.b16 {%0,%1,%2,%3}, [%4];"
        : "=r"(r[0]), "=r"(r[1]), "=r"(r[2]), "=r"(r[3]) : "r"(a));
}
__device__ __forceinline__ void mmaA(float* d, const u32* a, u32 b0, u32 b1) {
    asm volatile("mma.sync.aligned.m16n8k16.row.col.f32.bf16.bf16.f32 "
        "{%0,%1,%2,%3}, {%4,%5,%6,%7}, {%8,%9}, {%0,%1,%2,%3};"
        : "+f"(d[0]), "+f"(d[1]), "+f"(d[2]), "+f"(d[3])
        : "r"(a[0]), "r"(a[1]), "r"(a[2]), "r"(a[3]), "r"(b0), "r"(b1));
}
#define CPA16(dst, src) \
    asm volatile("cp.async.cg.shared.global [%0], [%1], 16;" :: "r"(dst), "l"(src))
#define CPA_COMMIT() asm volatile("cp.async.commit_group;")
#define CPA_WAIT1()  asm volatile("cp.async.wait_group 1;")
#define CPA_WAIT0()  asm volatile("cp.async.wait_group 0;")

// One k16 step for a warp tile m16 x n32: 3-term bf16 split => 12 HMMA.
__device__ __forceinline__ void mma_k16(float (&acc)[4][4], u32 aaddr, u32 alo_d,
                                        u32 baddr, u32 blo_d) {
    u32 ah[4], al[4];
    ldm4(ah, aaddr);
    ldm4(al, aaddr + alo_d);
#pragma unroll
    for (int p = 0; p < 2; p++) {
        u32 bh[4], bl[4];
        ldm4t(bh, baddr + p * 32);
        ldm4t(bl, baddr + p * 32 + blo_d);
        mmaA(acc[2 * p],     ah, bh[0], bh[1]);
        mmaA(acc[2 * p],     al, bh[0], bh[1]);
        mmaA(acc[2 * p],     ah, bl[0], bl[1]);
        mmaA(acc[2 * p + 1], ah, bh[2], bh[3]);
        mmaA(acc[2 * p + 1], al, bh[2], bh[3]);
        mmaA(acc[2 * p + 1], ah, bl[2], bl[3]);
    }
}

// ---------------- conversion kernels ----------------
// which: 0 -> x -> g_xhi/g_xlo ; 1 -> W -> g_Whi/g_Wlo ; 2 -> U -> g_Uhi/g_Ulo
// (destination pointers resolved in DEVICE code — device globals are not
//  addressable from host code.)
__global__ void __launch_bounds__(256) conv_split(
    const float4* __restrict__ src, int which, int n4)
{
    int i = blockIdx.x * blockDim.x + threadIdx.x;
    if (i >= n4) return;
    u32* hi; u32* lo;
    if (which == 0)      { hi = (u32*)g_xhi; lo = (u32*)g_xlo; }
    else if (which == 1) { hi = (u32*)g_Whi; lo = (u32*)g_Wlo; }
    else                 { hi = (u32*)g_Uhi; lo = (u32*)g_Ulo; }
    float4 v = src[i];
    __nv_bfloat16 hx = bfh(v.x), hy = bfh(v.y), hz = bfh(v.z), hw = bfh(v.w);
    hi[2 * i]     = pk(hx, hy);
    hi[2 * i + 1] = pk(hz, hw);
    lo[2 * i]     = pk(bfl(v.x, hx), bfl(v.y, hy));
    lo[2 * i + 1] = pk(bfl(v.z, hz), bfl(v.w, hw));
}

__global__ void copy_h0(const float* __restrict__ h0)
{
    int i = blockIdx.x * blockDim.x + threadIdx.x;
    if (i < Bb * Hh) g_h[i] = h0[i];
}

// ---------------- precompute (x-path) ----------------
// grid (48, 512): bx<32 -> W/Gx colblock (64 n), else U/Cx. by = t.
// cp.async double-buffered K-chunks of 64; per-chunk tiles A[64b][64k], B[64k][64n]
// hi/lo bf16, row stride 144B. Buffer = 36864B; two buffers.
#define PRE_SMEM (2 * 36864)

__global__ void __launch_bounds__(256) gemm_pre_tc(
    const float* __restrict__ Wb, const float* __restrict__ Ub)
{
    extern __shared__ char smp[];
    const u32 sb32 = smem_u32(smp);
    const int tid = threadIdx.x;
    const int cb = blockIdx.x, t = blockIdx.y;
    const bool isW = cb < 32;
    const __nv_bfloat16* whi = isW ? g_Whi : g_Uhi;
    const __nv_bfloat16* wlo = isW ? g_Wlo : g_Ulo;
    const float* bia = isW ? Wb : Ub;
    float* outg = isW ? g_Gx : g_Cx;
    const int ldn = isW ? 2048 : 1024;
    const int n0  = (isW ? cb : cb - 32) * 64;

    const int lane = tid & 31, w = tid >> 5;
    const int mt = (w & 3) * 16, nh = (w >> 2) * 32;
    const int row = lane & 15, lh = lane >> 4;

    float acc[4][4];
#pragma unroll
    for (int i = 0; i < 4; i++)
#pragma unroll
        for (int j = 0; j < 4; j++) acc[i][j] = 0.0f;

    auto do_copy = [&](int ch) {
        const int k0 = ch * 64;
        const u32 bufb = sb32 + (ch & 1) * 36864;
#pragma unroll
        for (int j = 0; j < 8; j++) {
            int idx = j * 256 + tid;
            int r = (idx >> 3) & 63, c8 = idx & 7;
            int sect = j >> 1;
            u32 dst; const __nv_bfloat16* src;
            if (sect == 0) {
                dst = bufb + r * 144 + c8 * 16;
                src = g_xhi + ((size_t)r * Tt + t) * Dd + k0 + c8 * 8;
            } else if (sect == 1) {
                dst = bufb + 9216 + r * 144 + c8 * 16;
                src = g_xlo + ((size_t)r * Tt + t) * Dd + k0 + c8 * 8;
            } else if (sect == 2) {
                dst = bufb + 18432 + r * 144 + c8 * 16;
                src = whi + (size_t)(k0 + r) * ldn + n0 + c8 * 8;
            } else {
                dst = bufb + 27648 + r * 144 + c8 * 16;
                src = wlo + (size_t)(k0 + r) * ldn + n0 + c8 * 8;
            }
            CPA16(dst, src);
        }
        CPA_COMMIT();
    };

    do_copy(0);
    for (int ch = 0; ch < 16; ch++) {
        if (ch + 1 < 16) { do_copy(ch + 1); CPA_WAIT1(); } else { CPA_WAIT0(); }
        __syncthreads();
        const u32 bufb = sb32 + (ch & 1) * 36864;
        const u32 abase = bufb + (mt + row) * 144 + lh * 16;
        const u32 bbase = bufb + 18432 + row * 144 + (nh + lh * 8) * 2;
#pragma unroll
        for (int k16 = 0; k16 < 4; k16++)
            mma_k16(acc, abase + k16 * 32, 9216, bbase + k16 * 2304, 9216);
        __syncthreads();
    }

    // epilogue: + bias, write [t][b][n]
    const int r0 = lane >> 2, c0 = (lane & 3) * 2;
#pragma unroll
    for (int na = 0; na < 4; na++) {
        int col = n0 + nh + na * 8 + c0;
        float2 bv = *reinterpret_cast<const float2*>(&bia[col]);
        *reinterpret_cast<float2*>(&outg[((size_t)t * Bb + mt + r0) * ldn + col]) =
            make_float2(acc[na][0] + bv.x, acc[na][1] + bv.y);
        *reinterpret_cast<float2*>(&outg[((size_t)t * Bb + mt + r0 + 8) * ldn + col]) =
            make_float2(acc[na][2] + bv.x, acc[na][3] + bv.y);
    }
}

// ---------------- persistent recurrence ----------------
// Phase A: 32 colblocks(64 n of 2048) x 4 ksplits(K=256).
// Phase B: 16 colblocks(64 n of 1024) x 8 ksplits(K=128).
// Weight slices resident in smem (bf16 hi/lo); h/rh staged hi/lo per step.
#define OFF_WAHI 0
#define OFF_WALO 36864
#define OFF_WBHI 73728
#define OFF_WBLO 92160
#define OFF_HHI  110592
#define OFF_HLO  144384
#define REC_SMEM 178176   // bytes

__global__ void __launch_bounds__(256) gru_persist(float* __restrict__ out)
{
    extern __shared__ char smp[];
    const u32 sb32 = smem_u32(smp);
    const int tid = threadIdx.x, bx = blockIdx.x;
    const int lane = tid & 31, w = tid >> 5;
    const int mt = (w & 3) * 16, nh = (w >> 2) * 32;
    const int row = lane & 15, lh = lane >> 4;
    const int r0 = lane >> 2, c0 = (lane & 3) * 2;
    const int ca = bx & 31, sa = bx >> 5;   // phase A decomposition
    const int cbp = bx & 15, sbp = bx >> 4; // phase B decomposition

    // ---- one-time: load resident weight slices (bf16 u32 copies) ----
    {
        const u32* wsh = reinterpret_cast<const u32*>(g_Whi);
        const u32* wsl = reinterpret_cast<const u32*>(g_Wlo);
        for (int i = tid; i < 256 * 32; i += 256) {
            int r = i >> 5, c = i & 31;
            size_t s = ((size_t)(Dd + sa * 256 + r) * 2048 + ca * 64) / 2 + c;
            *reinterpret_cast<u32*>(smp + OFF_WAHI + r * 144 + c * 4) = wsh[s];
            *reinterpret_cast<u32*>(smp + OFF_WALO + r * 144 + c * 4) = wsl[s];
        }
        const u32* ush = reinterpret_cast<const u32*>(g_Uhi);
        const u32* usl = reinterpret_cast<const u32*>(g_Ulo);
        for (int i = tid; i < 128 * 32; i += 256) {
            int r = i >> 5, c = i & 31;
            size_t s = ((size_t)(Dd + sbp * 128 + r) * 1024 + cbp * 64) / 2 + c;
            *reinterpret_cast<u32*>(smp + OFF_WBHI + r * 144 + c * 4) = ush[s];
            *reinterpret_cast<u32*>(smp + OFF_WBLO + r * 144 + c * 4) = usl[s];
        }
    }
    __syncthreads();

    const unsigned basec = ld_acq(&g_arrive);
    unsigned epoch = 0;

#define GRID_BAR()                                                           \
    do {                                                                     \
        __syncthreads();                                                     \
        epoch++;                                                             \
        if (tid == 0) {                                                      \
            red_release(&g_arrive);                                          \
            while ((unsigned)(ld_acq(&g_arrive) - basec) < epoch * Gblk) ;   \
        }                                                                    \
        __syncthreads();                                                     \
    } while (0)

    // stage h rows -> hi/lo bf16 tiles (stride 528B), STS.128 stores
    auto stage_h = [&](const float* src, int kbase, int nfl4) {
        const int m = tid >> 2;
        const int ko = (tid & 3) * (nfl4 * 4);
        const float4* s = reinterpret_cast<const float4*>(src + (size_t)m * 1024 + kbase + ko);
        char* dh = smp + OFF_HHI + m * 528 + ko * 2;
        char* dl = dh + (OFF_HLO - OFF_HHI);
#pragma unroll
        for (int j = 0; j < 16; j += 2) {
            if (j >= nfl4) break;
            float4 a = s[j], b = s[j + 1];
            __nv_bfloat16 h0 = bfh(a.x), h1 = bfh(a.y), h2 = bfh(a.z), h3 = bfh(a.w);
            __nv_bfloat16 h4 = bfh(b.x), h5 = bfh(b.y), h6 = bfh(b.z), h7 = bfh(b.w);
            *reinterpret_cast<uint4*>(dh + j * 8) =
                make_uint4(pk(h0, h1), pk(h2, h3), pk(h4, h5), pk(h6, h7));
            *reinterpret_cast<uint4*>(dl + j * 8) =
                make_uint4(pk(bfl(a.x, h0), bfl(a.y, h1)), pk(bfl(a.z, h2), bfl(a.w, h3)),
                           pk(bfl(b.x, h4), bfl(b.y, h5)), pk(bfl(b.z, h6), bfl(b.w, h7)));
        }
    };

    const u32 abase0 = sb32 + OFF_HHI + (mt + row) * 528 + lh * 16;
    const u32 baseA  = sb32 + OFF_WAHI + row * 144 + (nh + lh * 8) * 2;
    const u32 baseB  = sb32 + OFF_WBHI + row * 144 + (nh + lh * 8) * 2;

    for (int t = 0; t < Tt; ++t) {
        // ---------------- Phase A: gate partials ----------------
        {
            stage_h(g_h, sa * 256, 16);
            __syncthreads();
            float acc[4][4];
#pragma unroll
            for (int i = 0; i < 4; i++)
#pragma unroll
                for (int j = 0; j < 4; j++) acc[i][j] = 0.0f;
#pragma unroll
            for (int k16 = 0; k16 < 16; k16++)
                mma_k16(acc, abase0 + k16 * 32, OFF_HLO - OFF_HHI,
                        baseA + k16 * 2304, OFF_WALO - OFF_WAHI);
            float* pa = g_pA + (size_t)sa * (Bb * 2048);
#pragma unroll
            for (int na = 0; na < 4; na++) {
                int col = ca * 64 + nh + na * 8 + c0;
                *reinterpret_cast<float2*>(&pa[(size_t)(mt + r0) * 2048 + col]) =
                    make_float2(acc[na][0], acc[na][1]);
                *reinterpret_cast<float2*>(&pa[(size_t)(mt + r0 + 8) * 2048 + col]) =
                    make_float2(acc[na][2], acc[na][3]);
            }
        }
        GRID_BAR();

        // ---------------- A-reduce: sigmoid gates ----------------
        {
            const int flat = bx * 1024 + tid * 4;     // = b*2048 + n
            float4 a = *reinterpret_cast<const float4*>(&g_Gx[(size_t)t * (Bb * 2048) + flat]);
#pragma unroll
            for (int s = 0; s < 4; s++) {
                float4 p = *reinterpret_cast<const float4*>(&g_pA[(size_t)s * (Bb * 2048) + flat]);
                a.x += p.x; a.y += p.y; a.z += p.z; a.w += p.w;
            }
            float4 g;
            g.x = sigf(a.x); g.y = sigf(a.y); g.z = sigf(a.z); g.w = sigf(a.w);
            const int hidx = (bx >> 1) * 1024 + tid * 4;
            if (bx & 1) {
                *reinterpret_cast<float4*>(&g_u[hidx]) = g;
            } else {
                float4 h4 = *reinterpret_cast<const float4*>(&g_h[hidx]);
                *reinterpret_cast<float4*>(&g_rh[hidx]) =
                    make_float4(g.x * h4.x, g.y * h4.y, g.z * h4.z, g.w * h4.w);
            }
        }
        GRID_BAR();

        // ---------------- Phase B: candidate partials ----------------
        {
            stage_h(g_rh, sbp * 128, 8);
            __syncthreads();
            float acc[4][4];
#pragma unroll
            for (int i = 0; i < 4; i++)
#pragma unroll
                for (int j = 0; j < 4; j++) acc[i][j] = 0.0f;
#pragma unroll
            for (int k16 = 0; k16 < 8; k16++)
                mma_k16(acc, abase0 + k16 * 32, OFF_HLO - OFF_HHI,
                        baseB + k16 * 2304, OFF_WBLO - OFF_WBHI);
            float* pb = g_pB + (size_t)sbp * (Bb * 1024);
#pragma unroll
            for (int na = 0; na < 4; na++) {
                int col = cbp * 64 + nh + na * 8 + c0;
                *reinterpret_cast<float2*>(&pb[(size_t)(mt + r0) * 1024 + col]) =
                    make_float2(acc[na][0], acc[na][1]);
                *reinterpret_cast<float2*>(&pb[(size_t)(mt + r0 + 8) * 1024 + col]) =
                    make_float2(acc[na][2], acc[na][3]);
            }
        }
        GRID_BAR();

        // ---------------- B-reduce: tanh + state update ----------------
        {
            const int flat = bx * 512 + tid * 2;      // = b*1024 + n
            float2 a = *reinterpret_cast<const float2*>(&g_Cx[(size_t)t * (Bb * 1024) + flat]);
#pragma unroll
            for (int s = 0; s < 8; s++) {
                float2 p = *reinterpret_cast<const float2*>(&g_pB[(size_t)s * (Bb * 1024) + flat]);
                a.x += p.x; a.y += p.y;
            }
            float2 u2 = *reinterpret_cast<const float2*>(&g_u[flat]);
            float2 h2 = *reinterpret_cast<const float2*>(&g_h[flat]);
            float2 hn;
            hn.x = u2.x * h2.x + (1.0f - u2.x) * tanh_fast(a.x);
            hn.y = u2.y * h2.y + (1.0f - u2.y) * tanh_fast(a.y);
            *reinterpret_cast<float2*>(&g_h[flat]) = hn;
            const int b = flat >> 10, n = flat & 1023;
            *reinterpret_cast<float2*>(&out[((size_t)b * Tt + t) * 1024 + n]) = hn;
        }
        GRID_BAR();
    }
#undef GRID_BAR
}

extern "C" void kernel_launch(void* const* d_in, const int* in_sizes, int n_in,
                              void* d_out, int out_size)
{
    const float* x  = (const float*)d_in[0];
    const float* h0 = (const float*)d_in[1];
    const float* W  = (const float*)d_in[2];
    const float* Wb = (const float*)d_in[3];
    const float* U  = (const float*)d_in[4];
    const float* Ub = (const float*)d_in[5];
    float* out = (float*)d_out;

    cudaFuncSetAttribute(gemm_pre_tc, cudaFuncAttributeMaxDynamicSharedMemorySize, PRE_SMEM);
    cudaFuncSetAttribute(gru_persist, cudaFuncAttributeMaxDynamicSharedMemorySize, REC_SMEM);

    // one-time fp32 -> bf16 hi/lo splits (destinations resolved device-side)
    conv_split<<<(Bb * Tt * Dd / 4 + 255) / 256, 256>>>((const float4*)x, 0, Bb * Tt * Dd / 4);
    conv_split<<<(2048 * 2048 / 4 + 255) / 256, 256>>>((const float4*)W, 1, 2048 * 2048 / 4);
    conv_split<<<(2048 * 1024 / 4 + 255) / 256, 256>>>((const float4*)U, 2, 2048 * 1024 / 4);

    copy_h0<<<(Bb * Hh) / 256, 256>>>(h0);

    // x-path precompute: Gx[t][b][n], Cx[t][b][n]
    gemm_pre_tc<<<dim3(48, Tt), 256, PRE_SMEM>>>(Wb, Ub);

    // persistent recurrence
    gru_persist<<<Gblk, 256, REC_SMEM>>>(out);
}